// round 3
// baseline (speedup 1.0000x reference)
#include <cuda_runtime.h>

#define N_NODES 50000
#define N_EDGES 800000
#define IN_CH   256
#define HC      128
#define NCAT    384
#define EPS_F   1.000001f

// ---------------- scratch (static device arrays; no allocation) ----------------
__device__ float  g_Wcat[IN_CH * NCAT];                 // [256, 384] = Wl | Wu | Ws
__device__ float  g_WA[IN_CH * 8];                      // [256, 8] fused alpha weights
__device__ float  g_xm[3][(size_t)N_NODES * HC];        // 0: x@Wl, 1: x@Wu, 2: (x@Ws)*EPS
__device__ float2 g_alpha[4][N_NODES];                  // [src_l, dst_l, src_u, dst_u][n] = (h0,h1)
__device__ float  g_w[2][N_EDGES];                      // per-edge head-0 softmax weight
__device__ int    g_rp[2][N_NODES + 1];                 // CSR row ptr (tgt sorted)

// ---------------- 1) concat weights ----------------
__global__ void prep_wcat(const float* __restrict__ Wl,
                          const float* __restrict__ Wu,
                          const float* __restrict__ Ws) {
    int i = blockIdx.x * blockDim.x + threadIdx.x;
    if (i >= IN_CH * NCAT) return;
    int k = i / NCAT, c = i % NCAT;
    float v;
    if (c < 128)       v = Wl[k * 128 + c];
    else if (c < 256)  v = Wu[k * 128 + (c - 128)];
    else               v = Ws[k * 128 + (c - 256)];
    g_Wcat[i] = v;
}

// ---------------- 1b) fold attention vectors into weights: WA[k][col] ----------------
// col: 0 l_src_h0, 1 l_src_h1, 2 l_dst_h0, 3 l_dst_h1, 4 u_src_h0, ... 7 u_dst_h1
__global__ void prep_wa(const float* __restrict__ Wl, const float* __restrict__ Wu,
                        const float* __restrict__ asl, const float* __restrict__ adl,
                        const float* __restrict__ asu, const float* __restrict__ adu) {
    int i = blockIdx.x * blockDim.x + threadIdx.x;
    if (i >= IN_CH * 8) return;
    int k = i >> 3, col = i & 7;
    int set = col >> 2;            // 0 lower, 1 upper
    int typ = (col >> 1) & 1;      // 0 src, 1 dst
    int h   = col & 1;
    const float* W = set ? Wu : Wl;
    const float* a = set ? (typ ? adu : asu) : (typ ? adl : asl);
    float s = 0.f;
    #pragma unroll
    for (int c = 0; c < 64; c++)
        s = fmaf(W[k * 128 + h * 64 + c], a[h * 64 + c], s);
    g_WA[k * 8 + col] = s;
}

// ---------------- 2) row pointers via binary search (tgt arrays are sorted) ----------------
__global__ void rowptr_kernel(const int* __restrict__ ltgt, const int* __restrict__ utgt) {
    int t = blockIdx.x * blockDim.x + threadIdx.x;
    if (t > N_NODES) return;
    #pragma unroll
    for (int s = 0; s < 2; s++) {
        const int* tg = (s == 0) ? ltgt : utgt;
        int lo = 0, hi = N_EDGES;
        while (lo < hi) {
            int mid = (lo + hi) >> 1;
            if (tg[mid] < t) lo = mid + 1; else hi = mid;
        }
        g_rp[s][t] = lo;
    }
}

// ---------------- 3) fused SGEMM: x[50000,256] @ Wcat[256,384]  (+ alpha cols) ----------------
#define BM 128
#define BN 128
#define BK 16
#define TM 8
#define TN 8

__global__ __launch_bounds__(256) void gemm_kernel(const float* __restrict__ X) {
    __shared__ float As[BK][BM + 4];
    __shared__ float Bs[BK][BN + 4];
    __shared__ float WAs[BK][8];

    const int bx = blockIdx.x;          // 0..2 (N tiles of 128) -> matrix index
    const int by = blockIdx.y;          // M tiles
    const int tid = threadIdx.x;
    const int tx = tid & 15, ty = tid >> 4;
    const int m0 = by * BM;
    const bool do_alpha = (bx == 0);

    // A-load: 2 x float4 per thread
    const int ar = tid >> 2;            // 0..63 (rows ar, ar+64)
    const int aq = (tid & 3) * 4;       // k offset
    // B-load: 2 x float4 per thread
    const int bk = tid >> 4;            // 0..15
    const int bn = (tid & 15) * 8;

    // alpha mapping (bx==0 only): row r in tile, 4 cols
    const int arow = tid >> 1;          // 0..127
    const int acg  = (tid & 1) * 4;     // col group 0..3 or 4..7

    float acc[TM][TN] = {};
    float aacc[4] = {0.f, 0.f, 0.f, 0.f};

    for (int k0 = 0; k0 < IN_CH; k0 += BK) {
        #pragma unroll
        for (int r = 0; r < 2; r++) {
            int m = m0 + ar + r * 64;
            float4 v = make_float4(0.f, 0.f, 0.f, 0.f);
            if (m < N_NODES)
                v = *(const float4*)(X + (size_t)m * IN_CH + k0 + aq);
            As[aq + 0][ar + r * 64] = v.x;
            As[aq + 1][ar + r * 64] = v.y;
            As[aq + 2][ar + r * 64] = v.z;
            As[aq + 3][ar + r * 64] = v.w;
        }
        *(float4*)&Bs[bk][bn]     = *(const float4*)(g_Wcat + (size_t)(k0 + bk) * NCAT + bx * BN + bn);
        *(float4*)&Bs[bk][bn + 4] = *(const float4*)(g_Wcat + (size_t)(k0 + bk) * NCAT + bx * BN + bn + 4);
        if (do_alpha && tid < BK * 8)
            WAs[tid >> 3][tid & 7] = g_WA[(k0 + (tid >> 3)) * 8 + (tid & 7)];
        __syncthreads();

        #pragma unroll
        for (int k = 0; k < BK; k++) {
            float4 a0 = *(float4*)&As[k][ty * TM];
            float4 a1 = *(float4*)&As[k][ty * TM + 4];
            float4 b0 = *(float4*)&Bs[k][tx * TN];
            float4 b1 = *(float4*)&Bs[k][tx * TN + 4];
            float a[TM] = {a0.x, a0.y, a0.z, a0.w, a1.x, a1.y, a1.z, a1.w};
            float b[TN] = {b0.x, b0.y, b0.z, b0.w, b1.x, b1.y, b1.z, b1.w};
            #pragma unroll
            for (int i = 0; i < TM; i++)
                #pragma unroll
                for (int j = 0; j < TN; j++)
                    acc[i][j] = fmaf(a[i], b[j], acc[i][j]);
            if (do_alpha) {
                float av = As[k][arow];
                #pragma unroll
                for (int j = 0; j < 4; j++)
                    aacc[j] = fmaf(av, WAs[k][acg + j], aacc[j]);
            }
        }
        __syncthreads();
    }

    // main epilogue: bx selects the output matrix; scale skip by EPS
    const float scale = (bx == 2) ? EPS_F : 1.0f;
    float* dst = g_xm[bx];
    #pragma unroll
    for (int i = 0; i < TM; i++) {
        int m = m0 + ty * TM + i;
        if (m < N_NODES) {
            float4 v0 = make_float4(acc[i][0] * scale, acc[i][1] * scale,
                                    acc[i][2] * scale, acc[i][3] * scale);
            float4 v1 = make_float4(acc[i][4] * scale, acc[i][5] * scale,
                                    acc[i][6] * scale, acc[i][7] * scale);
            *(float4*)(dst + (size_t)m * HC + tx * TN)     = v0;
            *(float4*)(dst + (size_t)m * HC + tx * TN + 4) = v1;
        }
    }

    // alpha epilogue: leaky_relu then write two float2 slots
    if (do_alpha) {
        int m = m0 + arow;
        if (m < N_NODES) {
            #pragma unroll
            for (int j = 0; j < 4; j++)
                aacc[j] = (aacc[j] > 0.f) ? aacc[j] : 0.01f * aacc[j];
            int base = (tid & 1) * 2;   // half0 -> slots 0,1 (lower); half1 -> 2,3 (upper)
            g_alpha[base + 0][m] = make_float2(aacc[0], aacc[1]);   // src (h0,h1)
            g_alpha[base + 1][m] = make_float2(aacc[2], aacc[3]);   // dst (h0,h1)
        }
    }
}

// ---------------- 4) per-edge head-softmax weight (2 heads -> sigmoid) ----------------
// edge vals cancel (constant over the heads axis). w0 = 1/(1+exp(s1-s0)); w1 = 1-w0.
__global__ void edgew_kernel(const int* __restrict__ lsrc, const int* __restrict__ ltgt,
                             const int* __restrict__ usrc, const int* __restrict__ utgt) {
    int idx = blockIdx.x * blockDim.x + threadIdx.x;
    if (idx >= 2 * N_EDGES) return;
    int s = (idx >= N_EDGES) ? 1 : 0;
    int e = idx - s * N_EDGES;
    const int* src = s ? usrc : lsrc;
    const int* tgt = s ? utgt : ltgt;
    float2 as = g_alpha[s * 2][src[e]];
    float2 at = g_alpha[s * 2 + 1][tgt[e]];
    float d = (as.y + at.y) - (as.x + at.x);      // s1 - s0
    g_w[s][e] = 1.f / (1.f + __expf(d));
}

// ---------------- 5) fused aggregation: warp per target node, both edge sets ----------------
__global__ __launch_bounds__(256) void out_kernel(const int* __restrict__ lsrc,
                                                  const int* __restrict__ usrc,
                                                  float* __restrict__ out) {
    int warp = (blockIdx.x * blockDim.x + threadIdx.x) >> 5;
    int lane = threadIdx.x & 31;
    if (warp >= N_NODES) return;
    const int t = warp;
    const int head = lane >> 4;          // lanes 0-15 head0, 16-31 head1

    float4 acc = *(const float4*)(g_xm[2] + (size_t)t * HC + lane * 4);   // skip (already *EPS)

    #pragma unroll
    for (int s = 0; s < 2; s++) {
        const int*   src = (s == 0) ? lsrc : usrc;
        const float* xm  = g_xm[s];
        const float* wv  = g_w[s];
        const int beg = g_rp[s][t], end = g_rp[s][t + 1];
        int e = beg;
        // unroll-by-2 with index prefetch for MLP
        for (; e + 1 < end; e += 2) {
            int   sn0 = src[e],     sn1 = src[e + 1];
            float w00 = wv[e],      w01 = wv[e + 1];
            float4 v0 = *(const float4*)(xm + (size_t)sn0 * HC + lane * 4);
            float4 v1 = *(const float4*)(xm + (size_t)sn1 * HC + lane * 4);
            float wa = head ? (1.f - w00) : w00;
            float wb = head ? (1.f - w01) : w01;
            acc.x = fmaf(v0.x, wa, acc.x); acc.y = fmaf(v0.y, wa, acc.y);
            acc.z = fmaf(v0.z, wa, acc.z); acc.w = fmaf(v0.w, wa, acc.w);
            acc.x = fmaf(v1.x, wb, acc.x); acc.y = fmaf(v1.y, wb, acc.y);
            acc.z = fmaf(v1.z, wb, acc.z); acc.w = fmaf(v1.w, wb, acc.w);
        }
        if (e < end) {
            int   sn = src[e];
            float w0 = wv[e];
            float w  = head ? (1.f - w0) : w0;
            float4 v = *(const float4*)(xm + (size_t)sn * HC + lane * 4);
            acc.x = fmaf(v.x, w, acc.x); acc.y = fmaf(v.y, w, acc.y);
            acc.z = fmaf(v.z, w, acc.z); acc.w = fmaf(v.w, w, acc.w);
        }
    }
    acc.x = fmaxf(acc.x, 0.f);
    acc.y = fmaxf(acc.y, 0.f);
    acc.z = fmaxf(acc.z, 0.f);
    acc.w = fmaxf(acc.w, 0.f);
    *(float4*)(out + (size_t)t * HC + lane * 4) = acc;
}

// ---------------- launcher ----------------
extern "C" void kernel_launch(void* const* d_in, const int* in_sizes, int n_in,
                              void* d_out, int out_size) {
    const float* x    = (const float*)d_in[0];
    const int*   ltgt = (const int*)  d_in[1];
    const int*   lsrc = (const int*)  d_in[2];
    // d_in[3] lower_vals: unused (cancels in head-axis softmax)
    const int*   utgt = (const int*)  d_in[4];
    const int*   usrc = (const int*)  d_in[5];
    // d_in[6] upper_vals: unused
    const float* Wl   = (const float*)d_in[7];
    const float* asl  = (const float*)d_in[8];
    const float* adl  = (const float*)d_in[9];
    const float* Wu   = (const float*)d_in[10];
    const float* asu  = (const float*)d_in[11];
    const float* adu  = (const float*)d_in[12];
    const float* Ws   = (const float*)d_in[13];
    float* out = (float*)d_out;

    prep_wcat<<<(IN_CH * NCAT + 255) / 256, 256>>>(Wl, Wu, Ws);
    prep_wa<<<(IN_CH * 8 + 255) / 256, 256>>>(Wl, Wu, asl, adl, asu, adu);
    rowptr_kernel<<<(N_NODES + 1 + 255) / 256, 256>>>(ltgt, utgt);

    dim3 ggrid(NCAT / BN, (N_NODES + BM - 1) / BM);
    gemm_kernel<<<ggrid, 256>>>(x);

    edgew_kernel<<<(2 * N_EDGES + 255) / 256, 256>>>(lsrc, ltgt, usrc, utgt);

    out_kernel<<<(N_NODES * 32 + 255) / 256, 256>>>(lsrc, usrc, out);
}

// round 5
// speedup vs baseline: 1.5215x; 1.5215x over previous
#include <cuda_runtime.h>
#include <cuda_bf16.h>
#include <mma.h>
#include <cstdint>

using namespace nvcuda;

#define N_NODES 50000
#define N_EDGES 800000
#define IN_CH   256
#define HC      128
#define EPS_F   1.000001f

// ================= scratch (static device arrays; no allocation) =================
__device__ __nv_bfloat16 g_Bt[2][3][HC][IN_CH];     // [hi/lo][mat][n][k]  (B = W^T, bf16 split)
__device__ float  g_xm[3][(size_t)N_NODES * HC];    // 0: x@Wl, 1: x@Wu, 2: (x@Ws)*EPS
__device__ float2 g_alpha[4][N_NODES];              // [l_src, l_dst, u_src, u_dst][n] = (h0,h1)
__device__ float  g_w[2][N_EDGES];                  // per-edge head-0 softmax weight
__device__ int    g_rp[2][N_NODES + 1];             // CSR row ptr (tgt sorted)

// ================= 1) B = W^T split into bf16 hi/lo =================
__global__ void prep_bt(const float* __restrict__ Wl, const float* __restrict__ Wu,
                        const float* __restrict__ Ws) {
    int i = blockIdx.x * blockDim.x + threadIdx.x;
    if (i >= 3 * HC * IN_CH) return;
    int mat = i / (HC * IN_CH);
    int r   = i % (HC * IN_CH);
    int n = r / IN_CH, k = r % IN_CH;
    const float* W = (mat == 0) ? Wl : (mat == 1 ? Wu : Ws);
    float w = W[k * HC + n];
    __nv_bfloat16 hi = __float2bfloat16(w);
    __nv_bfloat16 lo = __float2bfloat16(w - __bfloat162float(hi));
    g_Bt[0][mat][n][k] = hi;
    g_Bt[1][mat][n][k] = lo;
}

// ================= 2) row pointers via binary search =================
__global__ void rowptr_kernel(const int* __restrict__ ltgt, const int* __restrict__ utgt) {
    int t = blockIdx.x * blockDim.x + threadIdx.x;
    if (t > N_NODES) return;
    #pragma unroll
    for (int s = 0; s < 2; s++) {
        const int* tg = (s == 0) ? ltgt : utgt;
        int lo = 0, hi = N_EDGES;
        while (lo < hi) {
            int mid = (lo + hi) >> 1;
            if (tg[mid] < t) lo = mid + 1; else hi = mid;
        }
        g_rp[s][t] = lo;
    }
}

// ================= 3) wmma bf16-split GEMM, fused alpha + EPS epilogue =================
// grid = (3 matrices, 391 M-tiles), 256 threads (8 warps, 4x2 warp grid, warp tile 32x64)
#define KC      64
#define NCHUNK  (IN_CH / KC)     // 4
#define LDA     72               // KC + 8 pad (bf16 elements); 144B row stride
#define SM_AVEC 0                // 256 floats: a_src[128] | a_dst[128]
#define SM_TILE 1024
#define A_HI    0
#define A_LO    (128 * LDA)
#define B_HI    (2 * 128 * LDA)
#define B_LO    (3 * 128 * LDA)
#define SM_TOTAL (SM_TILE + 4 * 128 * LDA * 2)   // 1024 + 73728 = 74752 B
#define LDC     132              // C staging: floats

__global__ __launch_bounds__(256) void gemm_wmma(const float* __restrict__ X,
                                                 const float* __restrict__ asl, const float* __restrict__ adl,
                                                 const float* __restrict__ asu, const float* __restrict__ adu) {
    extern __shared__ __align__(16) char smem[];
    __nv_bfloat16* tile = (__nv_bfloat16*)(smem + SM_TILE);
    float* avec = (float*)(smem + SM_AVEC);

    const int tid = threadIdx.x;
    const int wid = tid >> 5;
    const int bx  = blockIdx.x;                 // matrix 0=lower,1=upper,2=skip
    const int m0  = blockIdx.y * 128;
    const int wm  = wid & 3;                    // warp row: 4 x 32 rows
    const int wn  = wid >> 2;                   // warp col: 2 x 64 cols

    if (bx < 2) {
        const float* av = (tid < 128) ? (bx ? asu : asl) : (bx ? adu : adl);
        avec[tid] = av[tid & 127];
    }

    wmma::fragment<wmma::accumulator, 16, 16, 16, float> acc[2][4];
    #pragma unroll
    for (int i = 0; i < 2; i++)
        #pragma unroll
        for (int j = 0; j < 4; j++)
            wmma::fill_fragment(acc[i][j], 0.0f);

    // prefetch chunk 0 of X
    float4 xa[8];
    #pragma unroll
    for (int t = 0; t < 8; t++) {
        int f = tid + t * 256, row = f >> 4, k4 = f & 15;
        int m = m0 + row;
        xa[t] = (m < N_NODES) ? *(const float4*)(X + (size_t)m * IN_CH + k4 * 4)
                              : make_float4(0.f, 0.f, 0.f, 0.f);
    }

    for (int c = 0; c < NCHUNK; c++) {
        // --- store A (convert fp32 -> bf16 hi/lo) ---
        #pragma unroll
        for (int t = 0; t < 8; t++) {
            int f = tid + t * 256, row = f >> 4, k4 = f & 15;
            float4 v = xa[t];
            __nv_bfloat162 h0 = __floats2bfloat162_rn(v.x, v.y);
            __nv_bfloat162 h1 = __floats2bfloat162_rn(v.z, v.w);
            __nv_bfloat162 l0 = __floats2bfloat162_rn(v.x - __bfloat162float(h0.x), v.y - __bfloat162float(h0.y));
            __nv_bfloat162 l1 = __floats2bfloat162_rn(v.z - __bfloat162float(h1.x), v.w - __bfloat162float(h1.y));
            int e = row * LDA + k4 * 4;
            *(uint2*)(tile + A_HI + e) = make_uint2(*(uint32_t*)&h0, *(uint32_t*)&h1);
            *(uint2*)(tile + A_LO + e) = make_uint2(*(uint32_t*)&l0, *(uint32_t*)&l1);
        }
        // --- load + store B (bf16, L2-hot) ---
        #pragma unroll
        for (int t = 0; t < 4; t++) {
            int f = tid + t * 256, n = f >> 3, k8 = f & 7;
            uint4 bh = *(const uint4*)&g_Bt[0][bx][n][c * KC + k8 * 8];
            uint4 bl = *(const uint4*)&g_Bt[1][bx][n][c * KC + k8 * 8];
            int e = n * LDA + k8 * 8;
            *(uint4*)(tile + B_HI + e) = bh;
            *(uint4*)(tile + B_LO + e) = bl;
        }
        __syncthreads();

        // --- prefetch next X chunk (LDGs in flight during HMMA) ---
        if (c + 1 < NCHUNK) {
            #pragma unroll
            for (int t = 0; t < 8; t++) {
                int f = tid + t * 256, row = f >> 4, k4 = f & 15;
                int m = m0 + row;
                xa[t] = (m < N_NODES) ? *(const float4*)(X + (size_t)m * IN_CH + (c + 1) * KC + k4 * 4)
                                      : make_float4(0.f, 0.f, 0.f, 0.f);
            }
        }

        // --- HMMA: 4 k-steps of 16, 3 split terms ---
        #pragma unroll
        for (int ks = 0; ks < KC / 16; ks++) {
            wmma::fragment<wmma::matrix_a, 16, 16, 16, __nv_bfloat16, wmma::row_major> fa_hi[2], fa_lo[2];
            wmma::fragment<wmma::matrix_b, 16, 16, 16, __nv_bfloat16, wmma::col_major> fb_hi[4], fb_lo[4];
            #pragma unroll
            for (int i = 0; i < 2; i++) {
                const __nv_bfloat16* p = tile + (wm * 32 + i * 16) * LDA + ks * 16;
                wmma::load_matrix_sync(fa_hi[i], p + A_HI, LDA);
                wmma::load_matrix_sync(fa_lo[i], p + A_LO, LDA);
            }
            #pragma unroll
            for (int j = 0; j < 4; j++) {
                const __nv_bfloat16* p = tile + (wn * 64 + j * 16) * LDA + ks * 16;
                wmma::load_matrix_sync(fb_hi[j], p + B_HI, LDA);
                wmma::load_matrix_sync(fb_lo[j], p + B_LO, LDA);
            }
            #pragma unroll
            for (int i = 0; i < 2; i++)
                #pragma unroll
                for (int j = 0; j < 4; j++) {
                    wmma::mma_sync(acc[i][j], fa_hi[i], fb_hi[j], acc[i][j]);
                    wmma::mma_sync(acc[i][j], fa_lo[i], fb_hi[j], acc[i][j]);
                    wmma::mma_sync(acc[i][j], fa_hi[i], fb_lo[j], acc[i][j]);
                }
        }
        __syncthreads();
    }

    // --- epilogue: stage C in smem, fuse EPS / alpha / leaky_relu ---
    float* Cs = (float*)(smem + SM_TILE);       // 128 x 132 floats = 67584 B (fits tile area)
    #pragma unroll
    for (int i = 0; i < 2; i++)
        #pragma unroll
        for (int j = 0; j < 4; j++)
            wmma::store_matrix_sync(Cs + (wm * 32 + i * 16) * LDC + wn * 64 + j * 16,
                                    acc[i][j], LDC, wmma::mem_row_major);
    __syncthreads();

    {
        const int r = tid >> 1;                 // row in tile 0..127
        const int h = tid & 1;                  // half (= head) 0/1
        const int m = m0 + r;
        const float scale = (bx == 2) ? EPS_F : 1.0f;
        float ss = 0.f, dd = 0.f;
        if (m < N_NODES) {
            const float* crow = Cs + r * LDC + h * 64;
            float* dst = g_xm[bx] + (size_t)m * HC + h * 64;
            const float* avs = avec + h * 64;
            const float* avd = avec + 128 + h * 64;
            #pragma unroll
            for (int q = 0; q < 16; q++) {
                float4 v = *(const float4*)(crow + q * 4);
                if (bx < 2) {
                    ss = fmaf(v.x, avs[q*4+0], ss); ss = fmaf(v.y, avs[q*4+1], ss);
                    ss = fmaf(v.z, avs[q*4+2], ss); ss = fmaf(v.w, avs[q*4+3], ss);
                    dd = fmaf(v.x, avd[q*4+0], dd); dd = fmaf(v.y, avd[q*4+1], dd);
                    dd = fmaf(v.z, avd[q*4+2], dd); dd = fmaf(v.w, avd[q*4+3], dd);
                }
                v.x *= scale; v.y *= scale; v.z *= scale; v.w *= scale;
                *(float4*)(dst + q * 4) = v;
            }
        }
        if (bx < 2) {
            // pair lanes (tid, tid^1) hold head0/head1 for the same row
            float ss_o = __shfl_xor_sync(0xFFFFFFFF, ss, 1);
            float dd_o = __shfl_xor_sync(0xFFFFFFFF, dd, 1);
            if (h == 0 && m < N_NODES) {
                float s0 = (ss   > 0.f) ? ss   : 0.01f * ss;
                float s1 = (ss_o > 0.f) ? ss_o : 0.01f * ss_o;
                float d0 = (dd   > 0.f) ? dd   : 0.01f * dd;
                float d1 = (dd_o > 0.f) ? dd_o : 0.01f * dd_o;
                g_alpha[bx * 2 + 0][m] = make_float2(s0, s1);
                g_alpha[bx * 2 + 1][m] = make_float2(d0, d1);
            }
        }
    }
}

// ================= 4) per-edge head-softmax weight (2 heads -> sigmoid) =================
// edge vals cancel (constant over the heads axis). w0 = 1/(1+exp(s1-s0)); w1 = 1-w0.
__global__ void edgew_kernel(const int* __restrict__ lsrc, const int* __restrict__ ltgt,
                             const int* __restrict__ usrc, const int* __restrict__ utgt) {
    int idx = blockIdx.x * blockDim.x + threadIdx.x;
    if (idx >= 2 * N_EDGES) return;
    int s = (idx >= N_EDGES) ? 1 : 0;
    int e = idx - s * N_EDGES;
    const int* src = s ? usrc : lsrc;
    const int* tgt = s ? utgt : ltgt;
    float2 as = g_alpha[s * 2][src[e]];
    float2 at = g_alpha[s * 2 + 1][tgt[e]];
    float d = (as.y + at.y) - (as.x + at.x);      // s1 - s0
    g_w[s][e] = 1.f / (1.f + __expf(d));
}

// ================= 5) fused aggregation: warp per target node =================
__global__ __launch_bounds__(256) void out_kernel(const int* __restrict__ lsrc,
                                                  const int* __restrict__ usrc,
                                                  float* __restrict__ out) {
    int warp = (blockIdx.x * blockDim.x + threadIdx.x) >> 5;
    int lane = threadIdx.x & 31;
    if (warp >= N_NODES) return;
    const int t = warp;
    const int head = lane >> 4;

    float4 acc = *(const float4*)(g_xm[2] + (size_t)t * HC + lane * 4);   // skip (already *EPS)

    #pragma unroll
    for (int s = 0; s < 2; s++) {
        const int*   src = (s == 0) ? lsrc : usrc;
        const float* xm  = g_xm[s];
        const float* wv  = g_w[s];
        const int beg = g_rp[s][t], end = g_rp[s][t + 1];
        int e = beg;
        for (; e + 1 < end; e += 2) {
            int   sn0 = src[e],  sn1 = src[e + 1];
            float w00 = wv[e],   w01 = wv[e + 1];
            float4 v0 = *(const float4*)(xm + (size_t)sn0 * HC + lane * 4);
            float4 v1 = *(const float4*)(xm + (size_t)sn1 * HC + lane * 4);
            float wa = head ? (1.f - w00) : w00;
            float wb = head ? (1.f - w01) : w01;
            acc.x = fmaf(v0.x, wa, acc.x); acc.y = fmaf(v0.y, wa, acc.y);
            acc.z = fmaf(v0.z, wa, acc.z); acc.w = fmaf(v0.w, wa, acc.w);
            acc.x = fmaf(v1.x, wb, acc.x); acc.y = fmaf(v1.y, wb, acc.y);
            acc.z = fmaf(v1.z, wb, acc.z); acc.w = fmaf(v1.w, wb, acc.w);
        }
        if (e < end) {
            int   sn = src[e];
            float w0 = wv[e];
            float w  = head ? (1.f - w0) : w0;
            float4 v = *(const float4*)(xm + (size_t)sn * HC + lane * 4);
            acc.x = fmaf(v.x, w, acc.x); acc.y = fmaf(v.y, w, acc.y);
            acc.z = fmaf(v.z, w, acc.z); acc.w = fmaf(v.w, w, acc.w);
        }
    }
    acc.x = fmaxf(acc.x, 0.f);
    acc.y = fmaxf(acc.y, 0.f);
    acc.z = fmaxf(acc.z, 0.f);
    acc.w = fmaxf(acc.w, 0.f);
    *(float4*)(out + (size_t)t * HC + lane * 4) = acc;
}

// ================= launcher =================
extern "C" void kernel_launch(void* const* d_in, const int* in_sizes, int n_in,
                              void* d_out, int out_size) {
    const float* x    = (const float*)d_in[0];
    const int*   ltgt = (const int*)  d_in[1];
    const int*   lsrc = (const int*)  d_in[2];
    const int*   utgt = (const int*)  d_in[4];
    const int*   usrc = (const int*)  d_in[5];
    const float* Wl   = (const float*)d_in[7];
    const float* asl  = (const float*)d_in[8];
    const float* adl  = (const float*)d_in[9];
    const float* Wu   = (const float*)d_in[10];
    const float* asu  = (const float*)d_in[11];
    const float* adu  = (const float*)d_in[12];
    const float* Ws   = (const float*)d_in[13];
    float* out = (float*)d_out;

    cudaFuncSetAttribute(gemm_wmma, cudaFuncAttributeMaxDynamicSharedMemorySize, SM_TOTAL);

    prep_bt<<<(3 * HC * IN_CH + 255) / 256, 256>>>(Wl, Wu, Ws);
    rowptr_kernel<<<(N_NODES + 1 + 255) / 256, 256>>>(ltgt, utgt);

    dim3 ggrid(3, (N_NODES + 127) / 128);
    gemm_wmma<<<ggrid, 256, SM_TOTAL>>>(x, asl, adl, asu, adu);

    edgew_kernel<<<(2 * N_EDGES + 255) / 256, 256>>>(lsrc, ltgt, usrc, utgt);

    out_kernel<<<(N_NODES * 32 + 255) / 256, 256>>>(lsrc, usrc, out);
}

// round 6
// speedup vs baseline: 1.6183x; 1.0636x over previous
#include <cuda_runtime.h>
#include <cuda_bf16.h>
#include <cuda_fp16.h>
#include <mma.h>
#include <cstdint>

using namespace nvcuda;

#define N_NODES 50000
#define N_EDGES 800000
#define IN_CH   256
#define HC      128
#define EPS_F   1.000001f

// ================= scratch (static device arrays; no allocation) =================
__device__ __nv_bfloat16 g_Bt[2][3][HC][IN_CH];     // [hi/lo][mat][n][k]  (B = W^T, bf16 split)
__device__ __half g_xh[2][(size_t)N_NODES * HC];    // fp16 messages: x@Wl, x@Wu
__device__ float  g_xs[(size_t)N_NODES * HC];       // fp32 skip: (x@Ws)*EPS
__device__ float2 g_alpha[4][N_NODES];              // [l_src, l_dst, u_src, u_dst][n] = (h0,h1)
__device__ float  g_w[2][N_EDGES];                  // per-edge head-0 softmax weight
__device__ int    g_rp[2][N_NODES + 1];             // CSR row ptr (tgt sorted)

// ================= 1) B = W^T split into bf16 hi/lo =================
__global__ void prep_bt(const float* __restrict__ Wl, const float* __restrict__ Wu,
                        const float* __restrict__ Ws) {
    int i = blockIdx.x * blockDim.x + threadIdx.x;
    if (i >= 3 * HC * IN_CH) return;
    int mat = i / (HC * IN_CH);
    int r   = i % (HC * IN_CH);
    int n = r / IN_CH, k = r % IN_CH;
    const float* W = (mat == 0) ? Wl : (mat == 1 ? Wu : Ws);
    float w = W[k * HC + n];
    __nv_bfloat16 hi = __float2bfloat16(w);
    __nv_bfloat16 lo = __float2bfloat16(w - __bfloat162float(hi));
    g_Bt[0][mat][n][k] = hi;
    g_Bt[1][mat][n][k] = lo;
}

// ================= 2) row pointers via binary search =================
__global__ void rowptr_kernel(const int* __restrict__ ltgt, const int* __restrict__ utgt) {
    int t = blockIdx.x * blockDim.x + threadIdx.x;
    if (t > N_NODES) return;
    #pragma unroll
    for (int s = 0; s < 2; s++) {
        const int* tg = (s == 0) ? ltgt : utgt;
        int lo = 0, hi = N_EDGES;
        while (lo < hi) {
            int mid = (lo + hi) >> 1;
            if (tg[mid] < t) lo = mid + 1; else hi = mid;
        }
        g_rp[s][t] = lo;
    }
}

// ================= 3) wmma bf16-split GEMM, fused alpha + EPS epilogue =================
// grid = (3 matrices, 391 M-tiles), 256 threads (8 warps, 4x2 warp grid, warp tile 32x64)
#define KC      64
#define NCHUNK  (IN_CH / KC)     // 4
#define LDA     72               // KC + 8 pad (bf16 elements)
#define SM_AVEC 0                // 256 floats: a_src[128] | a_dst[128]
#define SM_TILE 1024
#define A_HI    0
#define A_LO    (128 * LDA)
#define B_HI    (2 * 128 * LDA)
#define B_LO    (3 * 128 * LDA)
#define SM_TOTAL (SM_TILE + 4 * 128 * LDA * 2)   // 74752 B
#define LDC     132              // C staging: floats

__global__ __launch_bounds__(256) void gemm_wmma(const float* __restrict__ X,
                                                 const float* __restrict__ asl, const float* __restrict__ adl,
                                                 const float* __restrict__ asu, const float* __restrict__ adu) {
    extern __shared__ __align__(16) char smem[];
    __nv_bfloat16* tile = (__nv_bfloat16*)(smem + SM_TILE);
    float* avec = (float*)(smem + SM_AVEC);

    const int tid = threadIdx.x;
    const int wid = tid >> 5;
    const int bx  = blockIdx.x;                 // matrix 0=lower,1=upper,2=skip
    const int m0  = blockIdx.y * 128;
    const int wm  = wid & 3;
    const int wn  = wid >> 2;

    if (bx < 2) {
        const float* av = (tid < 128) ? (bx ? asu : asl) : (bx ? adu : adl);
        avec[tid] = av[tid & 127];
    }

    wmma::fragment<wmma::accumulator, 16, 16, 16, float> acc[2][4];
    #pragma unroll
    for (int i = 0; i < 2; i++)
        #pragma unroll
        for (int j = 0; j < 4; j++)
            wmma::fill_fragment(acc[i][j], 0.0f);

    float4 xa[8];
    #pragma unroll
    for (int t = 0; t < 8; t++) {
        int f = tid + t * 256, row = f >> 4, k4 = f & 15;
        int m = m0 + row;
        xa[t] = (m < N_NODES) ? *(const float4*)(X + (size_t)m * IN_CH + k4 * 4)
                              : make_float4(0.f, 0.f, 0.f, 0.f);
    }

    for (int c = 0; c < NCHUNK; c++) {
        #pragma unroll
        for (int t = 0; t < 8; t++) {
            int f = tid + t * 256, row = f >> 4, k4 = f & 15;
            float4 v = xa[t];
            __nv_bfloat162 h0 = __floats2bfloat162_rn(v.x, v.y);
            __nv_bfloat162 h1 = __floats2bfloat162_rn(v.z, v.w);
            __nv_bfloat162 l0 = __floats2bfloat162_rn(v.x - __bfloat162float(h0.x), v.y - __bfloat162float(h0.y));
            __nv_bfloat162 l1 = __floats2bfloat162_rn(v.z - __bfloat162float(h1.x), v.w - __bfloat162float(h1.y));
            int e = row * LDA + k4 * 4;
            *(uint2*)(tile + A_HI + e) = make_uint2(*(uint32_t*)&h0, *(uint32_t*)&h1);
            *(uint2*)(tile + A_LO + e) = make_uint2(*(uint32_t*)&l0, *(uint32_t*)&l1);
        }
        #pragma unroll
        for (int t = 0; t < 4; t++) {
            int f = tid + t * 256, n = f >> 3, k8 = f & 7;
            uint4 bh = *(const uint4*)&g_Bt[0][bx][n][c * KC + k8 * 8];
            uint4 bl = *(const uint4*)&g_Bt[1][bx][n][c * KC + k8 * 8];
            int e = n * LDA + k8 * 8;
            *(uint4*)(tile + B_HI + e) = bh;
            *(uint4*)(tile + B_LO + e) = bl;
        }
        __syncthreads();

        if (c + 1 < NCHUNK) {
            #pragma unroll
            for (int t = 0; t < 8; t++) {
                int f = tid + t * 256, row = f >> 4, k4 = f & 15;
                int m = m0 + row;
                xa[t] = (m < N_NODES) ? *(const float4*)(X + (size_t)m * IN_CH + (c + 1) * KC + k4 * 4)
                                      : make_float4(0.f, 0.f, 0.f, 0.f);
            }
        }

        #pragma unroll
        for (int ks = 0; ks < KC / 16; ks++) {
            wmma::fragment<wmma::matrix_a, 16, 16, 16, __nv_bfloat16, wmma::row_major> fa_hi[2], fa_lo[2];
            wmma::fragment<wmma::matrix_b, 16, 16, 16, __nv_bfloat16, wmma::col_major> fb_hi[4], fb_lo[4];
            #pragma unroll
            for (int i = 0; i < 2; i++) {
                const __nv_bfloat16* p = tile + (wm * 32 + i * 16) * LDA + ks * 16;
                wmma::load_matrix_sync(fa_hi[i], p + A_HI, LDA);
                wmma::load_matrix_sync(fa_lo[i], p + A_LO, LDA);
            }
            #pragma unroll
            for (int j = 0; j < 4; j++) {
                const __nv_bfloat16* p = tile + (wn * 64 + j * 16) * LDA + ks * 16;
                wmma::load_matrix_sync(fb_hi[j], p + B_HI, LDA);
                wmma::load_matrix_sync(fb_lo[j], p + B_LO, LDA);
            }
            #pragma unroll
            for (int i = 0; i < 2; i++)
                #pragma unroll
                for (int j = 0; j < 4; j++) {
                    wmma::mma_sync(acc[i][j], fa_hi[i], fb_hi[j], acc[i][j]);
                    wmma::mma_sync(acc[i][j], fa_lo[i], fb_hi[j], acc[i][j]);
                    wmma::mma_sync(acc[i][j], fa_hi[i], fb_lo[j], acc[i][j]);
                }
        }
        __syncthreads();
    }

    // --- epilogue: stage C in smem; fuse alpha / EPS / fp16-message convert ---
    float* Cs = (float*)(smem + SM_TILE);
    #pragma unroll
    for (int i = 0; i < 2; i++)
        #pragma unroll
        for (int j = 0; j < 4; j++)
            wmma::store_matrix_sync(Cs + (wm * 32 + i * 16) * LDC + wn * 64 + j * 16,
                                    acc[i][j], LDC, wmma::mem_row_major);
    __syncthreads();

    {
        const int r = tid >> 1;                 // row in tile 0..127
        const int h = tid & 1;                  // half (= head) 0/1
        const int m = m0 + r;
        float ss = 0.f, dd = 0.f;
        if (m < N_NODES) {
            const float* crow = Cs + r * LDC + h * 64;
            if (bx == 2) {
                float* dst = g_xs + (size_t)m * HC + h * 64;
                #pragma unroll
                for (int q = 0; q < 16; q++) {
                    float4 v = *(const float4*)(crow + q * 4);
                    v.x *= EPS_F; v.y *= EPS_F; v.z *= EPS_F; v.w *= EPS_F;
                    *(float4*)(dst + q * 4) = v;
                }
            } else {
                __half* dst = g_xh[bx] + (size_t)m * HC + h * 64;
                const float* avs = avec + h * 64;
                const float* avd = avec + 128 + h * 64;
                #pragma unroll
                for (int q = 0; q < 16; q++) {
                    float4 v = *(const float4*)(crow + q * 4);
                    ss = fmaf(v.x, avs[q*4+0], ss); ss = fmaf(v.y, avs[q*4+1], ss);
                    ss = fmaf(v.z, avs[q*4+2], ss); ss = fmaf(v.w, avs[q*4+3], ss);
                    dd = fmaf(v.x, avd[q*4+0], dd); dd = fmaf(v.y, avd[q*4+1], dd);
                    dd = fmaf(v.z, avd[q*4+2], dd); dd = fmaf(v.w, avd[q*4+3], dd);
                    __half2 p0 = __floats2half2_rn(v.x, v.y);
                    __half2 p1 = __floats2half2_rn(v.z, v.w);
                    *(uint2*)(dst + q * 4) = make_uint2(*(uint32_t*)&p0, *(uint32_t*)&p1);
                }
            }
        }
        if (bx < 2) {
            float ss_o = __shfl_xor_sync(0xFFFFFFFF, ss, 1);
            float dd_o = __shfl_xor_sync(0xFFFFFFFF, dd, 1);
            if (h == 0 && m < N_NODES) {
                float s0 = (ss   > 0.f) ? ss   : 0.01f * ss;
                float s1 = (ss_o > 0.f) ? ss_o : 0.01f * ss_o;
                float d0 = (dd   > 0.f) ? dd   : 0.01f * dd;
                float d1 = (dd_o > 0.f) ? dd_o : 0.01f * dd_o;
                g_alpha[bx * 2 + 0][m] = make_float2(s0, s1);
                g_alpha[bx * 2 + 1][m] = make_float2(d0, d1);
            }
        }
    }
}

// ================= 4) per-edge head-softmax weight (2 heads -> sigmoid) =================
__global__ void edgew_kernel(const int* __restrict__ lsrc, const int* __restrict__ ltgt,
                             const int* __restrict__ usrc, const int* __restrict__ utgt) {
    int idx = blockIdx.x * blockDim.x + threadIdx.x;
    if (idx >= 2 * N_EDGES) return;
    int s = (idx >= N_EDGES) ? 1 : 0;
    int e = idx - s * N_EDGES;
    const int* src = s ? usrc : lsrc;
    const int* tgt = s ? utgt : ltgt;
    float2 as = g_alpha[s * 2][src[e]];
    float2 at = g_alpha[s * 2 + 1][tgt[e]];
    float d = (as.y + at.y) - (as.x + at.x);      // s1 - s0
    g_w[s][e] = 1.f / (1.f + __expf(d));
}

// ================= 5) fused aggregation: warp per target node, fp16 gathers =================
__global__ __launch_bounds__(256) void out_kernel(const int* __restrict__ lsrc,
                                                  const int* __restrict__ usrc,
                                                  float* __restrict__ out) {
    int warp = (blockIdx.x * blockDim.x + threadIdx.x) >> 5;
    int lane = threadIdx.x & 31;
    if (warp >= N_NODES) return;
    const int t = warp;
    const int head = lane >> 4;

    float4 acc = *(const float4*)(g_xs + (size_t)t * HC + lane * 4);   // skip (already *EPS)

    #pragma unroll
    for (int s = 0; s < 2; s++) {
        const int*   src = (s == 0) ? lsrc : usrc;
        const __half* xh = g_xh[s];
        const float* wv  = g_w[s];
        const int beg = g_rp[s][t], end = g_rp[s][t + 1];
        int e = beg;
        for (; e + 1 < end; e += 2) {
            int   sn0 = src[e],  sn1 = src[e + 1];
            float w00 = wv[e],   w01 = wv[e + 1];
            uint2 u0 = *(const uint2*)(xh + (size_t)sn0 * HC + lane * 4);
            uint2 u1 = *(const uint2*)(xh + (size_t)sn1 * HC + lane * 4);
            float wa = head ? (1.f - w00) : w00;
            float wb = head ? (1.f - w01) : w01;
            float2 a0 = __half22float2(*(__half2*)&u0.x);
            float2 a1 = __half22float2(*(__half2*)&u0.y);
            float2 b0 = __half22float2(*(__half2*)&u1.x);
            float2 b1 = __half22float2(*(__half2*)&u1.y);
            acc.x = fmaf(a0.x, wa, acc.x); acc.y = fmaf(a0.y, wa, acc.y);
            acc.z = fmaf(a1.x, wa, acc.z); acc.w = fmaf(a1.y, wa, acc.w);
            acc.x = fmaf(b0.x, wb, acc.x); acc.y = fmaf(b0.y, wb, acc.y);
            acc.z = fmaf(b1.x, wb, acc.z); acc.w = fmaf(b1.y, wb, acc.w);
        }
        if (e < end) {
            int   sn = src[e];
            float w0 = wv[e];
            float w  = head ? (1.f - w0) : w0;
            uint2 u = *(const uint2*)(xh + (size_t)sn * HC + lane * 4);
            float2 a0 = __half22float2(*(__half2*)&u.x);
            float2 a1 = __half22float2(*(__half2*)&u.y);
            acc.x = fmaf(a0.x, w, acc.x); acc.y = fmaf(a0.y, w, acc.y);
            acc.z = fmaf(a1.x, w, acc.z); acc.w = fmaf(a1.y, w, acc.w);
        }
    }
    acc.x = fmaxf(acc.x, 0.f);
    acc.y = fmaxf(acc.y, 0.f);
    acc.z = fmaxf(acc.z, 0.f);
    acc.w = fmaxf(acc.w, 0.f);
    *(float4*)(out + (size_t)t * HC + lane * 4) = acc;
}

// ================= launcher =================
extern "C" void kernel_launch(void* const* d_in, const int* in_sizes, int n_in,
                              void* d_out, int out_size) {
    const float* x    = (const float*)d_in[0];
    const int*   ltgt = (const int*)  d_in[1];
    const int*   lsrc = (const int*)  d_in[2];
    const int*   utgt = (const int*)  d_in[4];
    const int*   usrc = (const int*)  d_in[5];
    const float* Wl   = (const float*)d_in[7];
    const float* asl  = (const float*)d_in[8];
    const float* adl  = (const float*)d_in[9];
    const float* Wu   = (const float*)d_in[10];
    const float* asu  = (const float*)d_in[11];
    const float* adu  = (const float*)d_in[12];
    const float* Ws   = (const float*)d_in[13];
    float* out = (float*)d_out;

    cudaFuncSetAttribute(gemm_wmma, cudaFuncAttributeMaxDynamicSharedMemorySize, SM_TOTAL);

    prep_bt<<<(3 * HC * IN_CH + 255) / 256, 256>>>(Wl, Wu, Ws);
    rowptr_kernel<<<(N_NODES + 1 + 255) / 256, 256>>>(ltgt, utgt);

    dim3 ggrid(3, (N_NODES + 127) / 128);
    gemm_wmma<<<ggrid, 256, SM_TOTAL>>>(x, asl, adl, asu, adu);

    edgew_kernel<<<(2 * N_EDGES + 255) / 256, 256>>>(lsrc, ltgt, usrc, utgt);

    out_kernel<<<(N_NODES * 32 + 255) / 256, 256>>>(lsrc, usrc, out);
}